// round 1
// baseline (speedup 1.0000x reference)
#include <cuda_runtime.h>

#define TT 1024
#define OO 512
#define DD 256
#define HH 512

// Device scratch (no allocs allowed)
__device__ float g_ht[TT * HH];   // z_t @ W1[:D]            [1024,512]
__device__ float g_ho[OO * HH];   // z_o @ W1[D:] + b1       [512,512]
__device__ float g_ct[TT];        // 0.505 * <ht[t], W2>
__device__ float g_co[OO];        // 0.505 * <ho[o], W2> + b2

typedef unsigned long long u64;

__device__ __forceinline__ u64 add2(u64 a, u64 b) {
    u64 d; asm("add.rn.f32x2 %0,%1,%2;" : "=l"(d) : "l"(a), "l"(b)); return d;
}
__device__ __forceinline__ u64 fma2(u64 a, u64 b, u64 c) {
    u64 d; asm("fma.rn.f32x2 %0,%1,%2,%3;" : "=l"(d) : "l"(a), "l"(b), "l"(c)); return d;
}
__device__ __forceinline__ u64 dup2(float v) {
    u64 d; asm("mov.b64 %0,{%1,%1};" : "=l"(d) : "f"(v)); return d;
}

// ---------------------------------------------------------------------------
// GEMM: C[M,512] = A[M,256] @ B[256,512] (+bias). BM=128, BN=64, BK=16.
// 256 threads, micro-tile 8m x 4n per thread, f32x2 FFMA2 (m-pairs packed).
// ---------------------------------------------------------------------------
template <bool BIAS>
__global__ __launch_bounds__(256) void gemm_kernel(
    const float* __restrict__ A, const float* __restrict__ B,
    const float* __restrict__ bias, float* __restrict__ C)
{
    __shared__ float As[16][132];  // A^T tile [k][m], padded for 16B align + banks
    __shared__ float Bs[16][64];

    const int tid = threadIdx.x;
    const int tx = tid & 15;       // n
    const int ty = tid >> 4;       // m
    const int m0 = blockIdx.y * 128;
    const int n0 = blockIdx.x * 64;

    u64 acc[4][4];                 // [m-pair][n]
    #pragma unroll
    for (int i = 0; i < 4; i++)
        #pragma unroll
        for (int j = 0; j < 4; j++) acc[i][j] = 0ull;

    const int arow = tid >> 2;           // 0..63
    const int akv  = (tid & 3) << 2;     // k sub-offset 0,4,8,12
    const int brow = tid >> 4;           // 0..15
    const int bnv  = (tid & 15) << 2;

    for (int k0 = 0; k0 < DD; k0 += 16) {
        float4 va0 = *reinterpret_cast<const float4*>(&A[(m0 + arow) * DD + k0 + akv]);
        float4 va1 = *reinterpret_cast<const float4*>(&A[(m0 + arow + 64) * DD + k0 + akv]);
        float4 vb  = *reinterpret_cast<const float4*>(&B[(k0 + brow) * HH + n0 + bnv]);
        __syncthreads();   // previous compute done before overwriting tiles
        As[akv + 0][arow] = va0.x; As[akv + 1][arow] = va0.y;
        As[akv + 2][arow] = va0.z; As[akv + 3][arow] = va0.w;
        As[akv + 0][arow + 64] = va1.x; As[akv + 1][arow + 64] = va1.y;
        As[akv + 2][arow + 64] = va1.z; As[akv + 3][arow + 64] = va1.w;
        *reinterpret_cast<float4*>(&Bs[brow][bnv]) = vb;
        __syncthreads();

        #pragma unroll
        for (int k = 0; k < 16; k++) {
            const ulonglong2* ap = reinterpret_cast<const ulonglong2*>(&As[k][ty << 3]);
            ulonglong2 a01 = ap[0];   // {m0,m1},{m2,m3}
            ulonglong2 a23 = ap[1];   // {m4,m5},{m6,m7}
            float4 bq = *reinterpret_cast<const float4*>(&Bs[k][tx << 2]);
            u64 b0 = dup2(bq.x), b1v = dup2(bq.y), b2v = dup2(bq.z), b3v = dup2(bq.w);
            acc[0][0] = fma2(a01.x, b0,  acc[0][0]);
            acc[0][1] = fma2(a01.x, b1v, acc[0][1]);
            acc[0][2] = fma2(a01.x, b2v, acc[0][2]);
            acc[0][3] = fma2(a01.x, b3v, acc[0][3]);
            acc[1][0] = fma2(a01.y, b0,  acc[1][0]);
            acc[1][1] = fma2(a01.y, b1v, acc[1][1]);
            acc[1][2] = fma2(a01.y, b2v, acc[1][2]);
            acc[1][3] = fma2(a01.y, b3v, acc[1][3]);
            acc[2][0] = fma2(a23.x, b0,  acc[2][0]);
            acc[2][1] = fma2(a23.x, b1v, acc[2][1]);
            acc[2][2] = fma2(a23.x, b2v, acc[2][2]);
            acc[2][3] = fma2(a23.x, b3v, acc[2][3]);
            acc[3][0] = fma2(a23.y, b0,  acc[3][0]);
            acc[3][1] = fma2(a23.y, b1v, acc[3][1]);
            acc[3][2] = fma2(a23.y, b2v, acc[3][2]);
            acc[3][3] = fma2(a23.y, b3v, acc[3][3]);
        }
    }

    float4 bv = make_float4(0.f, 0.f, 0.f, 0.f);
    if (BIAS) bv = *reinterpret_cast<const float4*>(&bias[n0 + (tx << 2)]);

    #pragma unroll
    for (int ii = 0; ii < 4; ii++) {
        float2 f0 = *reinterpret_cast<float2*>(&acc[ii][0]);
        float2 f1 = *reinterpret_cast<float2*>(&acc[ii][1]);
        float2 f2 = *reinterpret_cast<float2*>(&acc[ii][2]);
        float2 f3 = *reinterpret_cast<float2*>(&acc[ii][3]);
        int m = m0 + (ty << 3) + (ii << 1);
        float4 r0 = make_float4(f0.x + bv.x, f1.x + bv.y, f2.x + bv.z, f3.x + bv.w);
        float4 r1 = make_float4(f0.y + bv.x, f1.y + bv.y, f2.y + bv.z, f3.y + bv.w);
        *reinterpret_cast<float4*>(&C[(u64)m * HH + n0 + (tx << 2)])       = r0;
        *reinterpret_cast<float4*>(&C[(u64)(m + 1) * HH + n0 + (tx << 2)]) = r1;
    }
}

// ---------------------------------------------------------------------------
// Per-row linear terms: ct[t] = 0.505*<ht[t],W2>, co[o] = 0.505*<ho[o],W2>+b2
// One warp per row. 1536 rows = 192 blocks x 8 warps.
// ---------------------------------------------------------------------------
__global__ __launch_bounds__(256) void reduce_kernel(
    const float* __restrict__ W2, const float* __restrict__ b2)
{
    int warp = (blockIdx.x * blockDim.x + threadIdx.x) >> 5;
    int lane = threadIdx.x & 31;
    const float* row;
    float* dst;
    float extra = 0.f;
    if (warp < TT) { row = g_ht + (u64)warp * HH; dst = g_ct + warp; }
    else { row = g_ho + (u64)(warp - TT) * HH; dst = g_co + (warp - TT); extra = b2[0]; }
    float s = 0.f;
    #pragma unroll
    for (int i = 0; i < 16; i++) s += row[lane + 32 * i] * W2[lane + 32 * i];
    #pragma unroll
    for (int off = 16; off; off >>= 1) s += __shfl_xor_sync(0xffffffffu, s, off);
    if (lane == 0) *dst = 0.505f * s + extra;
}

// ---------------------------------------------------------------------------
// Main pairwise kernel: out[t,o] = ct[t]+co[o] + sum_h |ht+ho| * (0.495*W2[h])
// 64x64 output tile per CTA (grid 8x16 = 128 CTAs), 256 thr, 4x4 micro (strided),
// H chunked by 64 into smem as float4 quads [hq][t]. f32x2 add/abs/fma inner.
// ---------------------------------------------------------------------------
__global__ __launch_bounds__(256) void pair_kernel(
    const float* __restrict__ W2, float* __restrict__ out)
{
    __shared__ float4 sA[16][65];      // [hq][t], padded
    __shared__ float4 sB[16][65];      // [hq][o]
    __shared__ float4 sW[HH / 4];      // 0.495*W2 quads

    const int tid = threadIdx.x;
    const int tx = tid & 15;           // o lane
    const int ty = tid >> 4;           // t lane
    const int t0 = blockIdx.y << 6;
    const int o0 = blockIdx.x << 6;

    if (tid < HH / 4) {
        float4 w = *reinterpret_cast<const float4*>(&W2[tid << 2]);
        w.x *= 0.495f; w.y *= 0.495f; w.z *= 0.495f; w.w *= 0.495f;
        sW[tid] = w;
    }

    u64 acc[4][4];
    #pragma unroll
    for (int i = 0; i < 4; i++)
        #pragma unroll
        for (int j = 0; j < 4; j++) acc[i][j] = 0ull;

    const int hs = tid & 15;           // hq for staging
    const int ts = tid >> 4;           // t/o base for staging
    const u64 SMASK = 0x7fffffff7fffffffULL;

    for (int c = 0; c < 8; c++) {      // 8 chunks of 64 h
        float4 va[4], vb[4];
        #pragma unroll
        for (int r = 0; r < 4; r++) {
            int t = ts + (r << 4);
            va[r] = *reinterpret_cast<const float4*>(&g_ht[(u64)(t0 + t) * HH + (c << 6) + (hs << 2)]);
            vb[r] = *reinterpret_cast<const float4*>(&g_ho[(u64)(o0 + t) * HH + (c << 6) + (hs << 2)]);
        }
        __syncthreads();   // previous chunk's reads complete
        #pragma unroll
        for (int r = 0; r < 4; r++) {
            sA[hs][ts + (r << 4)] = va[r];
            sB[hs][ts + (r << 4)] = vb[r];
        }
        __syncthreads();

        #pragma unroll
        for (int hq = 0; hq < 16; hq++) {
            ulonglong2 w = *reinterpret_cast<const ulonglong2*>(&sW[(c << 4) + hq]);
            ulonglong2 a[4], b[4];
            #pragma unroll
            for (int i = 0; i < 4; i++)
                a[i] = *reinterpret_cast<const ulonglong2*>(&sA[hq][ty + (i << 4)]);
            #pragma unroll
            for (int j = 0; j < 4; j++)
                b[j] = *reinterpret_cast<const ulonglong2*>(&sB[hq][tx + (j << 4)]);
            #pragma unroll
            for (int i = 0; i < 4; i++)
                #pragma unroll
                for (int j = 0; j < 4; j++) {
                    u64 x = add2(a[i].x, b[j].x) & SMASK;   // |ht+ho| packed pair
                    acc[i][j] = fma2(x, w.x, acc[i][j]);
                    u64 y = add2(a[i].y, b[j].y) & SMASK;
                    acc[i][j] = fma2(y, w.y, acc[i][j]);
                }
        }
    }

    float ctv[4], cov[4];
    #pragma unroll
    for (int i = 0; i < 4; i++) ctv[i] = g_ct[t0 + ty + (i << 4)];
    #pragma unroll
    for (int j = 0; j < 4; j++) cov[j] = g_co[o0 + tx + (j << 4)];
    #pragma unroll
    for (int i = 0; i < 4; i++)
        #pragma unroll
        for (int j = 0; j < 4; j++) {
            float2 p = *reinterpret_cast<float2*>(&acc[i][j]);
            out[(u64)(t0 + ty + (i << 4)) * OO + o0 + tx + (j << 4)]
                = ctv[i] + cov[j] + p.x + p.y;
        }
}

extern "C" void kernel_launch(void* const* d_in, const int* in_sizes, int n_in,
                              void* d_out, int out_size)
{
    const float* z_t = (const float*)d_in[0];   // [1024,256]
    const float* z_o = (const float*)d_in[1];   // [512,256]
    const float* W1  = (const float*)d_in[2];   // [512,512]
    const float* b1  = (const float*)d_in[3];   // [512]
    const float* W2  = (const float*)d_in[4];   // [512,1]
    const float* b2  = (const float*)d_in[5];   // [1]
    float* out = (float*)d_out;                 // [1024,512]

    float *ht_p, *ho_p;
    cudaGetSymbolAddress((void**)&ht_p, g_ht);
    cudaGetSymbolAddress((void**)&ho_p, g_ho);

    // ht = z_t @ W1[:256]            (M=1024 -> grid.y=8)
    gemm_kernel<false><<<dim3(8, 8), 256>>>(z_t, W1, nullptr, ht_p);
    // ho = z_o @ W1[256:] + b1       (M=512  -> grid.y=4)
    gemm_kernel<true><<<dim3(8, 4), 256>>>(z_o, W1 + (u64)DD * HH, b1, ho_p);
    // linear terms
    reduce_kernel<<<192, 256>>>(W2, b2);
    // pairwise |.| kernel
    pair_kernel<<<dim3(OO / 64, TT / 64), 256>>>(W2, out);
}